// round 9
// baseline (speedup 1.0000x reference)
#include <cuda_runtime.h>
#include <cuda_fp16.h>
#include <cstdint>
#include <cstddef>

#define F_IN  128
#define F_HID 64
#define F_OUT 40
#define MAXN  100032
#define MAXE  1600000
#define SCAN_B 512
#define MAXNB  256   // max scan blocks (N <= 131072)

// ---------------- scratch (no allocation allowed) ----------------
__device__ __align__(256) __half g_h1h[(size_t)MAXN * F_HID];  // fp16: dis[r]*(x@W1^T)[r]
__device__ __align__(256) float  g_agg1[(size_t)MAXN * F_HID]; // fp32 layer-1 aggregate
__device__ __align__(256) __half g_h3h[(size_t)MAXN * F_OUT];  // fp16: dis[r]*(relu@W2^T)[r]
__device__ float g_dis[MAXN];
__device__ int   g_cnt[MAXN];
__device__ int   g_rowptr[MAXN + 1];
__device__ int   g_cursor[MAXN];
__device__ int   g_blocksum[MAXNB];
__device__ int   g_perm[MAXE];
__device__ int   g_idx64;     // 1 if edge_index really is int64, 0 if int32

// ---------------- bit-cast helpers (no such intrinsics in CUDA) ----------------
__device__ __forceinline__ unsigned h2_as_u32(__half2 h) {
    return *reinterpret_cast<unsigned*>(&h);
}
__device__ __forceinline__ __half2 u32_as_h2(unsigned u) {
    return *reinterpret_cast<__half2*>(&u);
}

// ---------------- packed f32x2 helpers ----------------
__device__ __forceinline__ void ffma2(unsigned long long& d, unsigned long long a,
                                      unsigned long long b) {
    asm("fma.rn.f32x2 %0, %1, %2, %0;" : "+l"(d) : "l"(a), "l"(b));
}
__device__ __forceinline__ void unpack2(unsigned long long v, float& x, float& y) {
    asm("mov.b64 {%0, %1}, %2;" : "=f"(x), "=f"(y) : "l"(v));
}

__device__ __forceinline__ int edge_at(const void* ei, size_t i, int is64) {
    if (is64) return (int)((const long long*)ei)[i];
    return ((const int*)ei)[i];
}

// ---------------- K1: zero cnt + dtype detect ----------------
__global__ void k_zero_detect(const void* __restrict__ ei, int N) {
    int i = blockIdx.x * blockDim.x + threadIdx.x;
    if (i < N) g_cnt[i] = 0;
    if (i == 0) {
        const long long* p64 = (const long long*)ei;
        int bad = 0;
#pragma unroll
        for (int k = 0; k < 64; k++) {
            unsigned long long v = (unsigned long long)p64[k];
            if (v >= (unsigned long long)N) bad++;
        }
        g_idx64 = (bad == 0) ? 1 : 0;
    }
}

// ---------------- K2: in-degree count ----------------
__global__ void k_count(const void* __restrict__ ei, int E, int N) {
    int e = blockIdx.x * blockDim.x + threadIdx.x;
    int is64 = g_idx64;
    if (e < E) {
        int c = edge_at(ei, (size_t)E + e, is64);
        if ((unsigned)c < (unsigned)N) atomicAdd(&g_cnt[c], 1);
    }
}

// ---------------- K3: block scan of cnt (+dis) ----------------
__global__ __launch_bounds__(SCAN_B) void k_scan1(int N) {
    __shared__ int s[SCAN_B];
    int t = threadIdx.x;
    int i = blockIdx.x * SCAN_B + t;
    int val = (i < N) ? g_cnt[i] : 0;
    s[t] = val;
    __syncthreads();
#pragma unroll
    for (int off = 1; off < SCAN_B; off <<= 1) {
        int x = (t >= off) ? s[t - off] : 0;
        __syncthreads();
        s[t] += x;
        __syncthreads();
    }
    if (i < N) {
        g_rowptr[i] = s[t] - val;          // exclusive within block
        float d = (float)val;
        g_dis[i] = (d > 0.f) ? rsqrtf(d) : 0.f;
    }
    if (t == SCAN_B - 1) g_blocksum[blockIdx.x] = s[t];
}

// ---------------- K4: finish scan (each block redundantly scans blocksums) ----
__global__ __launch_bounds__(256) void k_scan23(int N, int nb) {
    __shared__ int s[MAXNB];
    __shared__ int sx[MAXNB + 1];
    int t = threadIdx.x;
    int val = (t < nb) ? g_blocksum[t] : 0;
    s[t] = val;
    __syncthreads();
#pragma unroll
    for (int off = 1; off < MAXNB; off <<= 1) {
        int x = (t >= off) ? s[t - off] : 0;
        __syncthreads();
        s[t] += x;
        __syncthreads();
    }
    sx[t] = s[t] - val;
    if (t == MAXNB - 1) sx[MAXNB] = s[t];
    __syncthreads();

    int i = blockIdx.x * 256 + t;
    if (i < N) {
        int v = g_rowptr[i] + sx[i / SCAN_B];
        g_rowptr[i] = v;
        g_cursor[i] = v;
    }
    if (blockIdx.x == 0 && t == 0) g_rowptr[N] = sx[MAXNB];
}

// ---------------- K5: CSR fill ----------------
__global__ void k_fill(const void* __restrict__ ei, int E, int N) {
    int e = blockIdx.x * blockDim.x + threadIdx.x;
    int is64 = g_idx64;
    if (e < E) {
        int r = edge_at(ei, (size_t)e, is64);
        int c = edge_at(ei, (size_t)E + e, is64);
        if ((unsigned)r < (unsigned)N && (unsigned)c < (unsigned)N) {
            int pos = atomicAdd(&g_cursor[c], 1);
            if ((unsigned)pos < (unsigned)MAXE) g_perm[pos] = r;
        }
    }
}

// ---------------- K6: GEMM1  h1h = fp16( dis .* (x @ W1^T) ) ----------------
// 256 thr, 128 rows x 64 cols. Thread: 4 row-pairs x 4 cols, FFMA2 core.
__global__ __launch_bounds__(256) void gemm1_kernel(const float* __restrict__ x,
                                                    const float* __restrict__ W1, int N) {
    __shared__ float2 xs2[32][65];   // [kk][rowpair]
    __shared__ float2 wd[32][65];    // [kk][j] duplicated (w,w)

    int tid = threadIdx.x;
    int tx = tid & 15;
    int ty = tid >> 4;
    int rbase = blockIdx.x * 128;

    unsigned long long acc[4][4];
#pragma unroll
    for (int r = 0; r < 4; r++)
#pragma unroll
        for (int c = 0; c < 4; c++) acc[r][c] = 0ull;

#pragma unroll 1
    for (int kp = 0; kp < 4; kp++) {
        __syncthreads();
#pragma unroll
        for (int it = 0; it < 16; it++) {
            int idx = it * 256 + tid;
            int rr = idx >> 5, kk = idx & 31;
            int gr = rbase + rr;
            float v = (gr < N) ? x[(size_t)gr * F_IN + kp * 32 + kk] : 0.f;
            ((float*)&xs2[kk][rr >> 1])[rr & 1] = v;
        }
#pragma unroll
        for (int it = 0; it < 8; it++) {
            int idx = it * 256 + tid;
            int j = idx >> 5, kk = idx & 31;
            float v = W1[j * F_IN + kp * 32 + kk];
            wd[kk][j] = make_float2(v, v);
        }
        __syncthreads();

#pragma unroll
        for (int kk = 0; kk < 32; kk++) {
            unsigned long long xp[4], wv[4];
#pragma unroll
            for (int r = 0; r < 4; r++)
                xp[r] = *(const unsigned long long*)&xs2[kk][4 * ty + r];
#pragma unroll
            for (int c = 0; c < 4; c++)
                wv[c] = *(const unsigned long long*)&wd[kk][4 * tx + c];
#pragma unroll
            for (int r = 0; r < 4; r++)
#pragma unroll
                for (int c = 0; c < 4; c++) ffma2(acc[r][c], xp[r], wv[c]);
        }
    }

#pragma unroll
    for (int r = 0; r < 4; r++) {
        int row0 = rbase + 2 * (4 * ty + r);
        if (row0 >= N) break;
        float d0 = g_dis[row0];
        float d1 = (row0 + 1 < N) ? g_dis[row0 + 1] : 0.f;
        float lo[4], hi[4];
#pragma unroll
        for (int c = 0; c < 4; c++) unpack2(acc[r][c], lo[c], hi[c]);
        {
            __half2 p0 = __floats2half2_rn(lo[0] * d0, lo[1] * d0);
            __half2 p1 = __floats2half2_rn(lo[2] * d0, lo[3] * d0);
            uint2 u = make_uint2(h2_as_u32(p0), h2_as_u32(p1));
            *(uint2*)&g_h1h[(size_t)row0 * F_HID + 4 * tx] = u;
        }
        if (row0 + 1 < N) {
            __half2 p0 = __floats2half2_rn(hi[0] * d1, hi[1] * d1);
            __half2 p1 = __floats2half2_rn(hi[2] * d1, hi[3] * d1);
            uint2 u = make_uint2(h2_as_u32(p0), h2_as_u32(p1));
            *(uint2*)&g_h1h[(size_t)(row0 + 1) * F_HID + 4 * tx] = u;
        }
    }
}

// ---------------- K8: GEMM2  h3h = fp16( dis .* (relu(agg1+b1) @ W2^T) ) ------
// 320 thr: tx=tid%10 -> cols 4tx..4tx+3; ty=tid/10 (0..31) -> rowpairs 2ty,2ty+1.
__global__ __launch_bounds__(320) void gemm2_kernel(const float* __restrict__ W2,
                                                    const float* __restrict__ b1, int N) {
    __shared__ float2 xs2[32][65];
    __shared__ float2 wd[32][41];

    int tid = threadIdx.x;
    int tx = tid % 10;
    int ty = tid / 10;
    int rbase = blockIdx.x * 128;

    unsigned long long acc[2][4];
#pragma unroll
    for (int r = 0; r < 2; r++)
#pragma unroll
        for (int c = 0; c < 4; c++) acc[r][c] = 0ull;

#pragma unroll 1
    for (int kp = 0; kp < 2; kp++) {
        __syncthreads();
        for (int idx = tid; idx < 128 * 32; idx += 320) {
            int rr = idx >> 5, kk = idx & 31;
            int gr = rbase + rr;
            float v = 0.f;
            if (gr < N)
                v = fmaxf(g_agg1[(size_t)gr * F_HID + kp * 32 + kk] + b1[kp * 32 + kk], 0.f);
            ((float*)&xs2[kk][rr >> 1])[rr & 1] = v;
        }
        for (int idx = tid; idx < F_OUT * 32; idx += 320) {
            int j = idx >> 5, kk = idx & 31;
            float v = W2[j * F_HID + kp * 32 + kk];
            wd[kk][j] = make_float2(v, v);
        }
        __syncthreads();

#pragma unroll
        for (int kk = 0; kk < 32; kk++) {
            unsigned long long xp[2], wv[4];
#pragma unroll
            for (int r = 0; r < 2; r++)
                xp[r] = *(const unsigned long long*)&xs2[kk][2 * ty + r];
#pragma unroll
            for (int c = 0; c < 4; c++)
                wv[c] = *(const unsigned long long*)&wd[kk][4 * tx + c];
#pragma unroll
            for (int r = 0; r < 2; r++)
#pragma unroll
                for (int c = 0; c < 4; c++) ffma2(acc[r][c], xp[r], wv[c]);
        }
    }

#pragma unroll
    for (int r = 0; r < 2; r++) {
        int row0 = rbase + 2 * (2 * ty + r);
        if (row0 >= N) break;
        float d0 = g_dis[row0];
        float d1 = (row0 + 1 < N) ? g_dis[row0 + 1] : 0.f;
        float lo[4], hi[4];
#pragma unroll
        for (int c = 0; c < 4; c++) unpack2(acc[r][c], lo[c], hi[c]);
        {
            __half2 p0 = __floats2half2_rn(lo[0] * d0, lo[1] * d0);
            __half2 p1 = __floats2half2_rn(lo[2] * d0, lo[3] * d0);
            uint2 u = make_uint2(h2_as_u32(p0), h2_as_u32(p1));
            *(uint2*)&g_h3h[(size_t)row0 * F_OUT + 4 * tx] = u;
        }
        if (row0 + 1 < N) {
            __half2 p0 = __floats2half2_rn(hi[0] * d1, hi[1] * d1);
            __half2 p1 = __floats2half2_rn(hi[2] * d1, hi[3] * d1);
            uint2 u = make_uint2(h2_as_u32(p0), h2_as_u32(p1));
            *(uint2*)&g_h3h[(size_t)(row0 + 1) * F_OUT + 4 * tx] = u;
        }
    }
}

// ---------------- K7: aggregation layer 1 (fp16 gather, fp32 accum) ----------
// warp per node; 2 groups of 16 lanes (one edge each); 16 chunks x 4 halves.
__global__ __launch_bounds__(256) void agg1_kernel(int N) {
    int wid = threadIdx.x >> 5;
    int lane = threadIdx.x & 31;
    int node = blockIdx.x * 8 + wid;
    if (node >= N) return;

    int start = g_rowptr[node];
    int end   = g_rowptr[node + 1];
    int half = lane >> 4;
    int ch   = lane & 15;

    const uint2* h = (const uint2*)g_h1h;   // 16 uint2 (=4 halves each) per row
    float4 acc = make_float4(0.f, 0.f, 0.f, 0.f);

#pragma unroll 4
    for (int k = start + half; k < end; k += 2) {
        int r = g_perm[k];
        uint2 v = __ldg(&h[(size_t)r * 16 + ch]);
        float2 fa = __half22float2(u32_as_h2(v.x));
        float2 fb = __half22float2(u32_as_h2(v.y));
        acc.x += fa.x; acc.y += fa.y; acc.z += fb.x; acc.w += fb.y;
    }
    acc.x += __shfl_down_sync(0xffffffffu, acc.x, 16);
    acc.y += __shfl_down_sync(0xffffffffu, acc.y, 16);
    acc.z += __shfl_down_sync(0xffffffffu, acc.z, 16);
    acc.w += __shfl_down_sync(0xffffffffu, acc.w, 16);

    if (lane < 16) {
        float di = g_dis[node];
        acc.x *= di; acc.y *= di; acc.z *= di; acc.w *= di;
        ((float4*)g_agg1)[(size_t)node * 16 + ch] = acc;
    }
}

// ---------------- K9: aggregation layer 2 + b2 -> out (fp32) ----------------
// warp per node; 3 groups of 10 lanes; 10 chunks x 4 halves; lanes 30,31 idle.
__global__ __launch_bounds__(256) void agg2_kernel(float* __restrict__ out,
                                                   const float* __restrict__ b2, int N) {
    int wid = threadIdx.x >> 5;
    int lane = threadIdx.x & 31;
    int node = blockIdx.x * 8 + wid;
    if (node >= N) return;

    int start = g_rowptr[node];
    int end   = g_rowptr[node + 1];
    int grp = lane / 10;
    int ch  = lane - grp * 10;

    const uint2* h = (const uint2*)g_h3h;   // 10 uint2 per row
    float4 acc = make_float4(0.f, 0.f, 0.f, 0.f);

    if (grp < 3) {
#pragma unroll 4
        for (int k = start + grp; k < end; k += 3) {
            int r = g_perm[k];
            uint2 v = __ldg(&h[(size_t)r * 10 + ch]);
            float2 fa = __half22float2(u32_as_h2(v.x));
            float2 fb = __half22float2(u32_as_h2(v.y));
            acc.x += fa.x; acc.y += fa.y; acc.z += fb.x; acc.w += fb.y;
        }
    }
    acc.x += __shfl_down_sync(0xffffffffu, acc.x, 10) + __shfl_down_sync(0xffffffffu, acc.x, 20);
    acc.y += __shfl_down_sync(0xffffffffu, acc.y, 10) + __shfl_down_sync(0xffffffffu, acc.y, 20);
    acc.z += __shfl_down_sync(0xffffffffu, acc.z, 10) + __shfl_down_sync(0xffffffffu, acc.z, 20);
    acc.w += __shfl_down_sync(0xffffffffu, acc.w, 10) + __shfl_down_sync(0xffffffffu, acc.w, 20);

    if (lane < 10) {
        float di = g_dis[node];
        float4 bb = __ldg(&((const float4*)b2)[ch]);
        acc.x = fmaf(acc.x, di, bb.x);
        acc.y = fmaf(acc.y, di, bb.y);
        acc.z = fmaf(acc.z, di, bb.z);
        acc.w = fmaf(acc.w, di, bb.w);
        ((float4*)out)[(size_t)node * 10 + ch] = acc;
    }
}

// ---------------- launch ----------------
extern "C" void kernel_launch(void* const* d_in, const int* in_sizes, int n_in,
                              void* d_out, int out_size) {
    const float* x = nullptr; const void* ei = nullptr;
    const float* W1 = nullptr; const float* b1 = nullptr;
    const float* W2 = nullptr; const float* b2 = nullptr;
    int x_sz = 0, ei_sz = 0;

    for (int i = 0; i < n_in; i++) {
        int s = in_sizes[i];
        if (s == 8192)       W1 = (const float*)d_in[i];
        else if (s == 2560)  W2 = (const float*)d_in[i];
        else if (s == 64)    b1 = (const float*)d_in[i];
        else if (s == 40)    b2 = (const float*)d_in[i];
        else if (s == 12800000) { x = (const float*)d_in[i]; x_sz = s; }
        else if (s == 3200000)  { ei = d_in[i]; ei_sz = s; }
    }
    if (!x || !ei || !W1 || !b1 || !W2 || !b2) {
        x  = (const float*)d_in[0];  x_sz  = in_sizes[0];
        ei = d_in[1];                ei_sz = in_sizes[1];
        W1 = (const float*)d_in[2];
        b1 = (const float*)d_in[3];
        W2 = (const float*)d_in[4];
        b2 = (const float*)d_in[5];
    }

    float* out = (float*)d_out;
    int N = x_sz / F_IN;
    int E = ei_sz / 2;
    if (N > MAXN) N = MAXN;
    if (E > MAXE) E = MAXE;
    int nb = (N + SCAN_B - 1) / SCAN_B;

    k_zero_detect<<<(N + 255) / 256, 256>>>(ei, N);
    k_count      <<<(E + 255) / 256, 256>>>(ei, E, N);
    k_scan1      <<<nb, SCAN_B>>>(N);
    k_scan23     <<<(N + 255) / 256, 256>>>(N, nb);
    k_fill       <<<(E + 255) / 256, 256>>>(ei, E, N);

    gemm1_kernel<<<(N + 127) / 128, 256>>>(x, W1, N);
    agg1_kernel <<<(N + 7) / 8, 256>>>(N);
    gemm2_kernel<<<(N + 127) / 128, 320>>>(W2, b1, N);
    agg2_kernel <<<(N + 7) / 8, 256>>>(out, b2, N);
}